// round 14
// baseline (speedup 1.0000x reference)
#include <cuda_runtime.h>
#include <cuda_bf16.h>
#include <math.h>
#include <stdint.h>

#define N 8192
#define D 512
#define BLK 128                 // row-stripe height / sub-tile size
#define NBLK (N / BLK)          // 64
#define TNT 256                 // col-stripe width (2 sub-tiles)
#define KC 64
#define KTOP 5
#define NTHREADS 512
#define GRID 132                // 132 CTAs x 8 jobs = 1056 jobs exactly
#define JOBS_PER_CTA 8

// Scratch (no cudaMalloc allowed)
static __device__ __nv_bfloat16 g_xnb[(size_t)N * D];      // 8 MB normalized rows
static __device__ float g_part[(size_t)N * NBLK * KTOP];   // 10.5 MB partial top-5
static __device__ float g_logrho[N];

// SMEM: A panel 128 KB + (mainloop: 2x32 KB B bufs | epilogue: Ccol 128x129 f32)
#define SA_BYTES (128 * 1024)
#define SB_BYTES (32 * 1024)
#define SB0_OFF  SA_BYTES
#define SMEM_TOTAL (SA_BYTES + 128 * 129 * 4)   // 197120 (>= A + 2*B = 196608)

// ---- PTX helpers ------------------------------------------------------------
__device__ __forceinline__ uint32_t smem_u32(const void* p) {
    uint32_t a;
    asm("{ .reg .u64 t; cvta.to.shared.u64 t, %1; cvt.u32.u64 %0, t; }" : "=r"(a) : "l"(p));
    return a;
}
__device__ __forceinline__ void ldsm_x4(uint32_t* r, uint32_t addr) {
    asm volatile("ldmatrix.sync.aligned.m8n8.x4.shared.b16 {%0,%1,%2,%3}, [%4];"
                 : "=r"(r[0]), "=r"(r[1]), "=r"(r[2]), "=r"(r[3]) : "r"(addr));
}
__device__ __forceinline__ void mma_bf16(float* d, const uint32_t* a,
                                         uint32_t b0, uint32_t b1) {
    asm volatile(
        "mma.sync.aligned.m16n8k16.row.col.f32.bf16.bf16.f32 "
        "{%0,%1,%2,%3}, {%4,%5,%6,%7}, {%8,%9}, {%0,%1,%2,%3};"
        : "+f"(d[0]), "+f"(d[1]), "+f"(d[2]), "+f"(d[3])
        : "r"(a[0]), "r"(a[1]), "r"(a[2]), "r"(a[3]), "r"(b0), "r"(b1));
}
__device__ __forceinline__ void cp16(uint32_t dst, const void* src) {
    asm volatile("cp.async.cg.shared.global [%0], [%1], 16;" :: "r"(dst), "l"(src));
}
__device__ __forceinline__ void cp_commit() {
    asm volatile("cp.async.commit_group;" ::: "memory");
}
__device__ __forceinline__ void cp_wait1() {
    asm volatile("cp.async.wait_group 1;" ::: "memory");
}
__device__ __forceinline__ void cp_wait0() {
    asm volatile("cp.async.wait_group 0;" ::: "memory");
}
__device__ __forceinline__ void ins5(float v, float& t0, float& t1, float& t2,
                                     float& t3, float& t4) {
    if (v > t0) {
        t0 = v;
        if (t0 > t1) { float tm = t0; t0 = t1; t1 = tm;
          if (t1 > t2) { tm = t1; t1 = t2; t2 = tm;
            if (t2 > t3) { tm = t2; t2 = t3; t3 = tm;
              if (t3 > t4) { tm = t3; t3 = t4; t4 = tm; } } } }
    }
}

// ---------------------------------------------------------------------------
// Kernel 1: row-normalize + cast to bf16.
// ---------------------------------------------------------------------------
__global__ void knorm(const float* __restrict__ x, __nv_bfloat16* __restrict__ xnb) {
    int row = blockIdx.x;
    int t = threadIdx.x;
    float4 v = ((const float4*)(x + (size_t)row * D))[t];
    float s = v.x * v.x + v.y * v.y + v.z * v.z + v.w * v.w;
    #pragma unroll
    for (int o = 16; o; o >>= 1) s += __shfl_xor_sync(0xffffffffu, s, o);
    __shared__ float ws[4];
    if ((t & 31) == 0) ws[t >> 5] = s;
    __syncthreads();
    float inv = rsqrtf(ws[0] + ws[1] + ws[2] + ws[3]);
    __nv_bfloat162 p0 = __floats2bfloat162_rn(v.x * inv, v.y * inv);
    __nv_bfloat162 p1 = __floats2bfloat162_rn(v.z * inv, v.w * inv);
    uint2 o2;
    o2.x = *(uint32_t*)&p0;
    o2.y = *(uint32_t*)&p1;
    ((uint2*)(xnb + (size_t)row * D))[t] = o2;
}

// ---------------------------------------------------------------------------
// Prefetch one 256x64 bf16 K-chunk of col-stripe J2 into B buffer `buf`.
// ---------------------------------------------------------------------------
__device__ __forceinline__ void prefetch_B(uint32_t sb, const __nv_bfloat16* xnb,
                                           int J2, int kb, int buf, int tid) {
    const uint32_t dstb = sb + SB0_OFF + (uint32_t)buf * SB_BYTES;
    const __nv_bfloat16* src = xnb + (size_t)J2 * TNT * D + kb * KC;
    #pragma unroll
    for (int it = 0; it < 4; it++) {
        int idx = tid + it * NTHREADS;       // 0..2047 16B chunks
        int n = idx >> 3, c16 = idx & 7;
        uint32_t off = (uint32_t)n * 128 + (uint32_t)c16 * 16;
        uint32_t sw = off ^ ((uint32_t)(n & 7) << 4);
        cp16(dstb + sw, src + (size_t)n * D + c16 * 8);
    }
    cp_commit();
}

// ---------------------------------------------------------------------------
// Kernel 2: symmetric-schedule bf16 GEMM + fused row/col top-5.
// 132 CTAs x 8 jobs (I row-stripe 128, J2 col-stripe 256, J2 >= I/2).
// Mainloop identical geometry to the 263us kernel: 16 warps (4M x 4N),
// warp tile 32x64, double-buffered 32KB cp.async chunks, A panel resident.
// Epilogue: per 128x128 sub-tile, register row-scan (+SMEM merge) and
// symmetry column-scan via SMEM staging in the dead B-buffer space.
// ---------------------------------------------------------------------------
__global__ void __launch_bounds__(NTHREADS, 1)
gemm_topk(const __nv_bfloat16* __restrict__ xnb, float* __restrict__ gpart) {
    extern __shared__ char smem[];
    const uint32_t sb = smem_u32(smem);
    float* epi = (float*)(smem + SB0_OFF);   // epilogue scratch (B space + pad)
    const int tid = threadIdx.x;
    const int wid = tid >> 5, lane = tid & 31;
    const int wm = wid & 3;          // 4 M-groups of 32 rows
    const int wn = wid >> 2;         // 4 N-groups of 64 cols

    const int q = lane >> 3;
    const int lr = lane & 7;
    const uint32_t swz = (uint32_t)lr << 4;

    uint32_t aoff[2], boff[4];
    #pragma unroll
    for (int mt = 0; mt < 2; mt++) {
        int arow = wm * 32 + mt * 16 + (q & 1) * 8 + lr;
        aoff[mt] = (uint32_t)arow * 1024 + (uint32_t)(q >> 1) * 16;
    }
    #pragma unroll
    for (int np = 0; np < 4; np++) {
        int bn = wn * 64 + np * 16 + (q & 1) * 8 + lr;
        boff[np] = (uint32_t)bn * 128 + (uint32_t)(q >> 1) * 16;
    }

    // locate first job (I, J2) for this CTA
    int I = 0, rem = blockIdx.x * JOBS_PER_CTA;
    while (true) {
        int cnt = 32 - (I >> 1);
        if (rem < cnt) break;
        rem -= cnt; I++;
    }
    int J2 = (I >> 1) + rem;
    int curI = -1;

    for (int jj = 0; jj < JOBS_PER_CTA; jj++) {
        // issue chunk0 early, overlap with A reload
        prefetch_B(sb, xnb, J2, 0, 0, tid);

        if (I != curI) {
            #pragma unroll
            for (int it = 0; it < 16; it++) {
                int idx = tid + it * NTHREADS;
                int r = idx >> 6, c16 = idx & 63;
                uint32_t off = (uint32_t)r * 1024 + (uint32_t)c16 * 16;
                uint32_t sw = off ^ ((uint32_t)(r & 7) << 4);
                *(uint4*)(smem + sw) =
                    *(const uint4*)(xnb + (size_t)(I * BLK + r) * D + c16 * 8);
            }
            curI = I;
        }

        float acc[2][8][4];
        #pragma unroll
        for (int mt = 0; mt < 2; mt++)
            #pragma unroll
            for (int nt = 0; nt < 8; nt++)
                #pragma unroll
                for (int j = 0; j < 4; j++) acc[mt][nt][j] = 0.f;

        #pragma unroll
        for (int kb = 0; kb < D / KC; kb++) {
            if (kb < 7) {
                prefetch_B(sb, xnb, J2, kb + 1, (kb + 1) & 1, tid);
                cp_wait1();
            } else {
                cp_wait0();
            }
            __syncthreads();

            const uint32_t bbase = sb + SB0_OFF + (uint32_t)(kb & 1) * SB_BYTES;

            #pragma unroll
            for (int k16 = 0; k16 < 4; k16++) {
                uint32_t a[2][4], b[4][4];
                #pragma unroll
                for (int mt = 0; mt < 2; mt++)
                    ldsm_x4(a[mt], sb + ((aoff[mt] + kb * 128 + k16 * 32) ^ swz));
                #pragma unroll
                for (int np = 0; np < 4; np++)
                    ldsm_x4(b[np], bbase + ((boff[np] + k16 * 32) ^ swz));
                #pragma unroll
                for (int mt = 0; mt < 2; mt++)
                    #pragma unroll
                    for (int nt = 0; nt < 8; nt++) {
                        const int np = nt >> 1, w = nt & 1;
                        mma_bf16(acc[mt][nt], a[mt], b[np][w], b[np][w + 2]);
                    }
            }
            __syncthreads();
        }

        // ================= epilogue =================
        const int J0 = 2 * J2;
        const int mysub = wn >> 1;           // this warp's 128-col sub-tile
        const int Jmine = J0 + mysub;

        // ---- row scans: transient per-thread top-5, padded-SMEM merge ----
        // mrg layout: row stride 83 floats; [sub*40 + w*5 + i]
        {
            const bool diag = (Jmine == I);
            #pragma unroll
            for (int mt = 0; mt < 2; mt++)
                #pragma unroll
                for (int half = 0; half < 2; half++) {
                    const int rl = wm * 32 + mt * 16 + half * 8 + (lane >> 2);
                    float t0 = -2.f, t1 = -2.f, t2 = -2.f, t3 = -2.f, t4 = -2.f;
                    #pragma unroll
                    for (int nt = 0; nt < 8; nt++)
                        #pragma unroll
                        for (int j = 0; j < 2; j++) {
                            int cl = (wn & 1) * 64 + nt * 8 + 2 * (lane & 3) + j;
                            float v = acc[mt][nt][half * 2 + j];
                            if (!(diag && cl == rl)) ins5(v, t0, t1, t2, t3, t4);
                        }
                    const int w = (wn & 1) * 4 + (lane & 3);
                    float* L = epi + rl * 83 + mysub * 40 + w * 5;
                    L[0] = t0; L[1] = t1; L[2] = t2; L[3] = t3; L[4] = t4;
                }
        }
        __syncthreads();
        {
            // 256 threads: sub = tid>>7, row = tid&127
            if (tid < 256) {
                const int sub = tid >> 7, row = tid & 127;
                const int Jsub = J0 + sub;
                if (Jsub >= I) {
                    float t0 = -2.f, t1 = -2.f, t2 = -2.f, t3 = -2.f, t4 = -2.f;
                    const float* L = epi + row * 83 + sub * 40;
                    #pragma unroll 8
                    for (int i = 0; i < 40; i++) ins5(L[i], t0, t1, t2, t3, t4);
                    float* dst = gpart + ((size_t)(I * BLK + row) * NBLK + Jsub) * KTOP;
                    dst[0] = t0; dst[1] = t1; dst[2] = t2; dst[3] = t3; dst[4] = t4;
                }
            }
        }
        __syncthreads();

        // ---- column scans (symmetry): stage sub-tile, scan columns ----
        #pragma unroll
        for (int s = 0; s < 2; s++) {
            const int Jsub = J0 + s;
            if (Jsub > I) {
                if (mysub == s) {
                    #pragma unroll
                    for (int mt = 0; mt < 2; mt++)
                        #pragma unroll
                        for (int nt = 0; nt < 8; nt++)
                            #pragma unroll
                            for (int half = 0; half < 2; half++)
                                #pragma unroll
                                for (int j = 0; j < 2; j++) {
                                    int r = wm * 32 + mt * 16 + half * 8 + (lane >> 2);
                                    int c = (wn & 1) * 64 + nt * 8 + 2 * (lane & 3) + j;
                                    epi[r * 129 + c] = acc[mt][nt][half * 2 + j];
                                }
                }
                __syncthreads();
                if (tid < 128) {
                    float t0 = -2.f, t1 = -2.f, t2 = -2.f, t3 = -2.f, t4 = -2.f;
                    #pragma unroll 8
                    for (int r = 0; r < 128; r++)
                        ins5(epi[r * 129 + tid], t0, t1, t2, t3, t4);
                    float* dst = gpart + ((size_t)(Jsub * BLK + tid) * NBLK + I) * KTOP;
                    dst[0] = t0; dst[1] = t1; dst[2] = t2; dst[3] = t3; dst[4] = t4;
                }
                __syncthreads();
            }
        }

        // advance to next job
        if (++J2 == 32) { I++; J2 = I >> 1; }
    }
}

// ---------------------------------------------------------------------------
// Kernel 3: merge 64 partial top-5 lists per row -> log(mean_rho + eps).
// ---------------------------------------------------------------------------
__global__ void kfinal(const float* __restrict__ gpart, float* __restrict__ lr) {
    int row = blockIdx.x * 256 + threadIdx.x;
    const float4* p = (const float4*)(gpart + (size_t)row * NBLK * KTOP);
    float t0 = -2.f, t1 = -2.f, t2 = -2.f, t3 = -2.f, t4 = -2.f;
    #pragma unroll 8
    for (int i = 0; i < NBLK * KTOP / 4; i++) {
        float4 v = p[i];
        ins5(v.x, t0, t1, t2, t3, t4);
        ins5(v.y, t0, t1, t2, t3, t4);
        ins5(v.z, t0, t1, t2, t3, t4);
        ins5(v.w, t0, t1, t2, t3, t4);
    }
    float sum = sqrtf(fmaxf(2.f - 2.f * t0, 0.f))
              + sqrtf(fmaxf(2.f - 2.f * t1, 0.f))
              + sqrtf(fmaxf(2.f - 2.f * t2, 0.f))
              + sqrtf(fmaxf(2.f - 2.f * t3, 0.f))
              + sqrtf(fmaxf(2.f - 2.f * t4, 0.f));
    lr[row] = logf(sum * (1.f / KTOP) + 1e-8f);
}

// ---------------------------------------------------------------------------
// Kernel 4: out = -mean(logrho)
// ---------------------------------------------------------------------------
__global__ void kred(const float* __restrict__ lr, float* __restrict__ out) {
    int t = threadIdx.x;
    float s = 0.f;
    for (int i = t; i < N; i += 256) s += lr[i];
    #pragma unroll
    for (int o = 16; o; o >>= 1) s += __shfl_xor_sync(0xffffffffu, s, o);
    __shared__ float ws[8];
    if ((t & 31) == 0) ws[t >> 5] = s;
    __syncthreads();
    if (t == 0) {
        float tot = 0.f;
        #pragma unroll
        for (int i = 0; i < 8; i++) tot += ws[i];
        out[0] = -tot / (float)N;
    }
}

// ---------------------------------------------------------------------------
extern "C" void kernel_launch(void* const* d_in, const int* in_sizes, int n_in,
                              void* d_out, int out_size) {
    (void)in_sizes; (void)n_in; (void)out_size;
    const float* x = (const float*)d_in[0];
    float* out = (float*)d_out;

    __nv_bfloat16* xnb; cudaGetSymbolAddress((void**)&xnb, g_xnb);
    float* gpart;       cudaGetSymbolAddress((void**)&gpart, g_part);
    float* lrho;        cudaGetSymbolAddress((void**)&lrho, g_logrho);

    cudaFuncSetAttribute(gemm_topk, cudaFuncAttributeMaxDynamicSharedMemorySize, SMEM_TOTAL);

    knorm<<<N, 128>>>(x, xnb);
    gemm_topk<<<GRID, NTHREADS, SMEM_TOTAL>>>(xnb, gpart);
    kfinal<<<N / 256, 256>>>(gpart, lrho);
    kred<<<1, 256>>>(lrho, out);
}

// round 16
// speedup vs baseline: 1.4456x; 1.4456x over previous
#include <cuda_runtime.h>
#include <cuda_bf16.h>
#include <math.h>
#include <stdint.h>

#define N 8192
#define D 512
#define TM 128            // M rows per tile
#define TNT 256           // cols per job stripe
#define KC 64             // K chunk
#define KTOP 5
#define NTHREADS 512
#define GRID 148
#define NJOBS 2048        // 64 M-tiles x 32 col stripes

// Scratch (no cudaMalloc allowed)
static __device__ __nv_bfloat16 g_xnb[(size_t)N * D];     // 8 MB normalized rows
static __device__ float g_part[(size_t)N * 4 * KTOP];     // per-row, 4 writer slots
static __device__ float g_logrho[N];

// SMEM: A panel 128 KB + 2x32 KB B buffers + 10 KB merge area (4 lists/row)
#define SA_BYTES (128 * 1024)
#define SB_BYTES (32 * 1024)
#define SB0_OFF  SA_BYTES                       // 131072
#define SMRG_OFF (SB0_OFF + 2 * SB_BYTES)       // 196608
#define SMEM_TOTAL (SMRG_OFF + 128 * 20 * 4)    // 206848

// ---- PTX helpers ------------------------------------------------------------
__device__ __forceinline__ uint32_t smem_u32(const void* p) {
    uint32_t a;
    asm("{ .reg .u64 t; cvta.to.shared.u64 t, %1; cvt.u32.u64 %0, t; }" : "=r"(a) : "l"(p));
    return a;
}
__device__ __forceinline__ void ldsm_x4(uint32_t* r, uint32_t addr) {
    asm volatile("ldmatrix.sync.aligned.m8n8.x4.shared.b16 {%0,%1,%2,%3}, [%4];"
                 : "=r"(r[0]), "=r"(r[1]), "=r"(r[2]), "=r"(r[3]) : "r"(addr));
}
__device__ __forceinline__ void mma_bf16(float* d, const uint32_t* a,
                                         uint32_t b0, uint32_t b1) {
    asm volatile(
        "mma.sync.aligned.m16n8k16.row.col.f32.bf16.bf16.f32 "
        "{%0,%1,%2,%3}, {%4,%5,%6,%7}, {%8,%9}, {%0,%1,%2,%3};"
        : "+f"(d[0]), "+f"(d[1]), "+f"(d[2]), "+f"(d[3])
        : "r"(a[0]), "r"(a[1]), "r"(a[2]), "r"(a[3]), "r"(b0), "r"(b1));
}
__device__ __forceinline__ void cp16(uint32_t dst, const void* src) {
    asm volatile("cp.async.cg.shared.global [%0], [%1], 16;" :: "r"(dst), "l"(src));
}
__device__ __forceinline__ void cp_commit() {
    asm volatile("cp.async.commit_group;" ::: "memory");
}
__device__ __forceinline__ void cp_wait1() {
    asm volatile("cp.async.wait_group 1;" ::: "memory");
}
__device__ __forceinline__ void cp_wait0() {
    asm volatile("cp.async.wait_group 0;" ::: "memory");
}
__device__ __forceinline__ void ins5(float v, float& t0, float& t1, float& t2,
                                     float& t3, float& t4) {
    if (v > t0) {
        t0 = v;
        if (t0 > t1) { float tm = t0; t0 = t1; t1 = tm;
          if (t1 > t2) { tm = t1; t1 = t2; t2 = tm;
            if (t2 > t3) { tm = t2; t2 = t3; t3 = tm;
              if (t3 > t4) { tm = t3; t3 = t4; t4 = tm; } } } }
    }
}

// ---------------------------------------------------------------------------
// Kernel 0: poison partial slots (graph-replay safe; slots may be unwritten).
// ---------------------------------------------------------------------------
__global__ void ginit(float* __restrict__ gpart) {
    gpart[blockIdx.x * 1024 + threadIdx.x] = -2.f;   // N*4*5 = 163840 = 160*1024
}

// ---------------------------------------------------------------------------
// Kernel 1: row-normalize + cast to bf16. One block (128 threads) per row.
// ---------------------------------------------------------------------------
__global__ void knorm(const float* __restrict__ x, __nv_bfloat16* __restrict__ xnb) {
    int row = blockIdx.x;
    int t = threadIdx.x;
    float4 v = ((const float4*)(x + (size_t)row * D))[t];
    float s = v.x * v.x + v.y * v.y + v.z * v.z + v.w * v.w;
    #pragma unroll
    for (int o = 16; o; o >>= 1) s += __shfl_xor_sync(0xffffffffu, s, o);
    __shared__ float ws[4];
    if ((t & 31) == 0) ws[t >> 5] = s;
    __syncthreads();
    float inv = rsqrtf(ws[0] + ws[1] + ws[2] + ws[3]);
    __nv_bfloat162 p0 = __floats2bfloat162_rn(v.x * inv, v.y * inv);
    __nv_bfloat162 p1 = __floats2bfloat162_rn(v.z * inv, v.w * inv);
    uint2 o2;
    o2.x = *(uint32_t*)&p0;
    o2.y = *(uint32_t*)&p1;
    ((uint2*)(xnb + (size_t)row * D))[t] = o2;
}

// ---------------------------------------------------------------------------
// Prefetch one 256x64 bf16 K-chunk of col stripe `ct` into B buffer `buf`.
// ---------------------------------------------------------------------------
__device__ __forceinline__ void prefetch_B(uint32_t sb, const __nv_bfloat16* xnb,
                                           int ct, int kb, int buf, int tid) {
    const uint32_t dstb = sb + SB0_OFF + (uint32_t)buf * SB_BYTES;
    const __nv_bfloat16* src = xnb + (size_t)ct * TNT * D + kb * KC;
    #pragma unroll
    for (int it = 0; it < 4; it++) {
        int idx = tid + it * NTHREADS;       // 0..2047 16B chunks
        int n = idx >> 3, c16 = idx & 7;
        uint32_t off = (uint32_t)n * 128 + (uint32_t)c16 * 16;
        uint32_t sw = off ^ ((uint32_t)(n & 7) << 4);
        cp16(dstb + sw, src + (size_t)n * D + c16 * 8);
    }
    cp_commit();
}

// ---------------------------------------------------------------------------
// Kernel 2: persistent-schedule bf16 GEMM + fused per-row top-5 in registers.
// 148 CTAs, contiguous ranges of 2048 jobs (job = Mtile*32 + colstripe).
// Mainloop geometry identical to the 263us kernel: 16 warps (4M x 4N),
// warp tile 32x64, 32KB double-buffered cp.async chunks, A panel resident.
// Private top-5 persists across jobs. Flush (only on M-tile change, <=2 per
// CTA, + final): shfl-merge the 4 lanes sharing a row -> 4 lists/row in a
// 10KB SMEM area -> one gpart slot (slot = bid & 3; an M-tile is touched by
// at most 4 consecutive CTAs, so slots never collide).
// ---------------------------------------------------------------------------
__global__ void __launch_bounds__(NTHREADS, 1)
gemm_topk(const __nv_bfloat16* __restrict__ xnb, float* __restrict__ gpart) {
    extern __shared__ char smem[];
    const uint32_t sb = smem_u32(smem);
    float* mrg = (float*)(smem + SMRG_OFF);   // [128][20] merge area
    const int tid = threadIdx.x;
    const int wid = tid >> 5, lane = tid & 31;
    const int wm = wid & 3;          // 4 M-groups of 32 rows
    const int wn = wid >> 2;         // 4 N-groups of 64 cols

    const int q = lane >> 3;
    const int lr = lane & 7;
    const uint32_t swz = (uint32_t)lr << 4;

    uint32_t aoff[2], boff[4];
    #pragma unroll
    for (int mt = 0; mt < 2; mt++) {
        int arow = wm * 32 + mt * 16 + (q & 1) * 8 + lr;
        aoff[mt] = (uint32_t)arow * 1024 + (uint32_t)(q >> 1) * 16;
    }
    #pragma unroll
    for (int np = 0; np < 4; np++) {
        int bn = wn * 64 + np * 16 + (q & 1) * 8 + lr;
        boff[np] = (uint32_t)bn * 128 + (uint32_t)(q >> 1) * 16;
    }

    // local row index per slot (global row = curI*128 + rowl)
    int rowl[4];
    #pragma unroll
    for (int mt = 0; mt < 2; mt++)
        #pragma unroll
        for (int half = 0; half < 2; half++)
            rowl[mt * 2 + half] = wm * 32 + mt * 16 + half * 8 + (lane >> 2);

    float tp[4][5];
    #pragma unroll
    for (int s = 0; s < 4; s++)
        #pragma unroll
        for (int i = 0; i < 5; i++) tp[s][i] = -2.f;

    const int j0 = (blockIdx.x * NJOBS) / GRID;
    const int j1 = ((blockIdx.x + 1) * NJOBS) / GRID;
    const int slot = blockIdx.x & 3;
    int curI = -1;

    // ---- flush lambda-equivalent (macro-free, called 3x max) ----
    // merges lane groups via shfl, writes 4 lists/row to mrg, reduces, stores.
    auto flush = [&](int I) {
        // in-register merge of the 4 lanes sharing each row (offsets 1, 2)
        #pragma unroll
        for (int s = 0; s < 4; s++) {
            #pragma unroll
            for (int off = 1; off <= 2; off <<= 1) {
                float c0 = tp[s][0], c1 = tp[s][1], c2 = tp[s][2],
                      c3 = tp[s][3], c4 = tp[s][4];
                float v0 = __shfl_xor_sync(0xffffffffu, c0, off);
                float v1 = __shfl_xor_sync(0xffffffffu, c1, off);
                float v2 = __shfl_xor_sync(0xffffffffu, c2, off);
                float v3 = __shfl_xor_sync(0xffffffffu, c3, off);
                float v4 = __shfl_xor_sync(0xffffffffu, c4, off);
                ins5(v0, tp[s][0], tp[s][1], tp[s][2], tp[s][3], tp[s][4]);
                ins5(v1, tp[s][0], tp[s][1], tp[s][2], tp[s][3], tp[s][4]);
                ins5(v2, tp[s][0], tp[s][1], tp[s][2], tp[s][3], tp[s][4]);
                ins5(v3, tp[s][0], tp[s][1], tp[s][2], tp[s][3], tp[s][4]);
                ins5(v4, tp[s][0], tp[s][1], tp[s][2], tp[s][3], tp[s][4]);
            }
        }
        if ((lane & 3) == 0) {
            #pragma unroll
            for (int s = 0; s < 4; s++) {
                float* L = mrg + rowl[s] * 20 + wn * 5;
                #pragma unroll
                for (int i = 0; i < 5; i++) L[i] = tp[s][i];
            }
        }
        __syncthreads();
        if (tid < 128) {
            float t0 = -2.f, t1 = -2.f, t2 = -2.f, t3 = -2.f, t4 = -2.f;
            #pragma unroll
            for (int i = 0; i < 20; i++)
                ins5(mrg[tid * 20 + i], t0, t1, t2, t3, t4);
            float* dst = gpart + ((size_t)(I * TM + tid) * 4 + slot) * KTOP;
            dst[0] = t0; dst[1] = t1; dst[2] = t2; dst[3] = t3; dst[4] = t4;
        }
        __syncthreads();
        #pragma unroll
        for (int s = 0; s < 4; s++)
            #pragma unroll
            for (int i = 0; i < 5; i++) tp[s][i] = -2.f;
    };

    // prologue: prefetch first job's chunk0 (buf0)
    prefetch_B(sb, xnb, j0 & 31, 0, 0, tid);

    for (int job = j0; job < j1; job++) {
        const int I = job >> 5;
        const int ct = job & 31;
        const int col0 = ct * TNT;

        if (I != curI) {
            if (curI >= 0) flush(curI);
            // ---- load resident A panel (M-tile I), swizzled ----
            #pragma unroll
            for (int it = 0; it < 16; it++) {
                int idx = tid + it * NTHREADS;
                int r = idx >> 6, c16 = idx & 63;
                uint32_t off = (uint32_t)r * 1024 + (uint32_t)c16 * 16;
                uint32_t sw = off ^ ((uint32_t)(r & 7) << 4);
                *(uint4*)(smem + sw) =
                    *(const uint4*)(xnb + (size_t)(I * TM + r) * D + c16 * 8);
            }
            curI = I;
        }

        float acc[2][8][4];
        #pragma unroll
        for (int mt = 0; mt < 2; mt++)
            #pragma unroll
            for (int nt = 0; nt < 8; nt++)
                #pragma unroll
                for (int j = 0; j < 4; j++) acc[mt][nt][j] = 0.f;

        #pragma unroll
        for (int kb = 0; kb < D / KC; kb++) {
            if (kb < 7) {
                prefetch_B(sb, xnb, ct, kb + 1, (kb + 1) & 1, tid);
                cp_wait1();
            } else if (job + 1 < j1) {
                prefetch_B(sb, xnb, (job + 1) & 31, 0, 0, tid);  // next job chunk0
                cp_wait1();
            } else {
                cp_wait0();
            }
            __syncthreads();   // chunk kb arrived; A panel (if reloaded) visible

            const uint32_t bbase = sb + SB0_OFF + (uint32_t)(kb & 1) * SB_BYTES;

            #pragma unroll
            for (int k16 = 0; k16 < 4; k16++) {
                uint32_t a[2][4], b[4][4];
                #pragma unroll
                for (int mt = 0; mt < 2; mt++)
                    ldsm_x4(a[mt], sb + ((aoff[mt] + kb * 128 + k16 * 32) ^ swz));
                #pragma unroll
                for (int np = 0; np < 4; np++)
                    ldsm_x4(b[np], bbase + ((boff[np] + k16 * 32) ^ swz));
                #pragma unroll
                for (int mt = 0; mt < 2; mt++)
                    #pragma unroll
                    for (int nt = 0; nt < 8; nt++) {
                        const int np = nt >> 1, w = nt & 1;
                        mma_bf16(acc[mt][nt], a[mt], b[np][w], b[np][w + 2]);
                    }
            }
            __syncthreads();   // buffer reads done before its refill next iter
        }

        // ---- scan accumulators into private top-5 (register-only) ----
        #pragma unroll
        for (int mt = 0; mt < 2; mt++)
            #pragma unroll
            for (int half = 0; half < 2; half++) {
                const int s = mt * 2 + half;
                const int rg = curI * TM + rowl[s];
                #pragma unroll
                for (int nt = 0; nt < 8; nt++)
                    #pragma unroll
                    for (int j = 0; j < 2; j++) {
                        float v = acc[mt][nt][half * 2 + j];
                        int cg = col0 + wn * 64 + nt * 8 + 2 * (lane & 3) + j;
                        if (cg != rg)
                            ins5(v, tp[s][0], tp[s][1], tp[s][2], tp[s][3], tp[s][4]);
                    }
            }
    }

    flush(curI);
}

// ---------------------------------------------------------------------------
// Kernel 3: merge 4 slot lists per row (20 values) -> log(mean_rho + eps).
// ---------------------------------------------------------------------------
__global__ void kfinal(const float* __restrict__ gpart, float* __restrict__ lr) {
    int row = blockIdx.x * 256 + threadIdx.x;
    const float4* p = (const float4*)(gpart + (size_t)row * 4 * KTOP);
    float t0 = -2.f, t1 = -2.f, t2 = -2.f, t3 = -2.f, t4 = -2.f;
    #pragma unroll
    for (int i = 0; i < 5; i++) {
        float4 v = p[i];
        ins5(v.x, t0, t1, t2, t3, t4);
        ins5(v.y, t0, t1, t2, t3, t4);
        ins5(v.z, t0, t1, t2, t3, t4);
        ins5(v.w, t0, t1, t2, t3, t4);
    }
    float sum = sqrtf(fmaxf(2.f - 2.f * t0, 0.f))
              + sqrtf(fmaxf(2.f - 2.f * t1, 0.f))
              + sqrtf(fmaxf(2.f - 2.f * t2, 0.f))
              + sqrtf(fmaxf(2.f - 2.f * t3, 0.f))
              + sqrtf(fmaxf(2.f - 2.f * t4, 0.f));
    lr[row] = logf(sum * (1.f / KTOP) + 1e-8f);
}

// ---------------------------------------------------------------------------
// Kernel 4: out = -mean(logrho)
// ---------------------------------------------------------------------------
__global__ void kred(const float* __restrict__ lr, float* __restrict__ out) {
    int t = threadIdx.x;
    float s = 0.f;
    for (int i = t; i < N; i += 256) s += lr[i];
    #pragma unroll
    for (int o = 16; o; o >>= 1) s += __shfl_xor_sync(0xffffffffu, s, o);
    __shared__ float ws[8];
    if ((t & 31) == 0) ws[t >> 5] = s;
    __syncthreads();
    if (t == 0) {
        float tot = 0.f;
        #pragma unroll
        for (int i = 0; i < 8; i++) tot += ws[i];
        out[0] = -tot / (float)N;
    }
}

// ---------------------------------------------------------------------------
extern "C" void kernel_launch(void* const* d_in, const int* in_sizes, int n_in,
                              void* d_out, int out_size) {
    (void)in_sizes; (void)n_in; (void)out_size;
    const float* x = (const float*)d_in[0];
    float* out = (float*)d_out;

    __nv_bfloat16* xnb; cudaGetSymbolAddress((void**)&xnb, g_xnb);
    float* gpart;       cudaGetSymbolAddress((void**)&gpart, g_part);
    float* lrho;        cudaGetSymbolAddress((void**)&lrho, g_logrho);

    cudaFuncSetAttribute(gemm_topk, cudaFuncAttributeMaxDynamicSharedMemorySize, SMEM_TOTAL);

    ginit<<<160, 1024>>>(gpart);
    knorm<<<N, 128>>>(x, xnb);
    gemm_topk<<<GRID, NTHREADS, SMEM_TOTAL>>>(xnb, gpart);
    kfinal<<<N / 256, 256>>>(gpart, lrho);
    kred<<<1, 256>>>(lrho, out);
}